// round 8
// baseline (speedup 1.0000x reference)
#include <cuda_runtime.h>
#include <cuda_fp16.h>
#include <cstdint>

// ---------------------------------------------------------------------------
// RNNT joiner, fused single-pass GEMM at 32 warps/SM:
//   out[m,v] = sum_d relu(src[b,t,d]+tgt[b,u,d]) * W[v,d] + bias[v]
// M=65536, N=1024, K=1024. GEMM core = R7 (512 thr, 16 warps of 32x32,
// CTA 128x128x32, 4-stage cp.async, 2 CTAs/SM, 64-reg cap). A tile
// (2 src rows x 64 tgt rows) built in-kernel with HADD2/HMAX2 from
// fp16-preconverted src/tgt staged via cp.async (R6 scheme, now spread
// over 512 threads: 1 x 16B segment per thread).
// ---------------------------------------------------------------------------

#define B_ 4
#define T_ 256
#define U_ 64
#define D_ 1024
#define V_ 1024
#define M_ (B_ * T_ * U_)

#define TILE_M 128
#define TILE_N 128
#define TILE_K 32
#define KITERS (D_ / TILE_K) /* 32 */
#define NTHREADS 512
#define NSTAGE 4

#define PITCH 80                      /* 64B row + 16B pad */
#define STAGE_BYTES (128 * PITCH)     /* 10240 */
#define TGT_STAGE (64 * PITCH)        /* 5120 */
#define SRC_STAGE 256                 /* 2 rows x 80B, padded */

// smem: B[4] | A[2] | tgt[4] | src[4]  = 82944 B -> 2 CTAs/SM
#define OFF_B 0
#define OFF_A (NSTAGE * STAGE_BYTES)            /* 40960 */
#define OFF_T (OFF_A + 2 * STAGE_BYTES)         /* 61440 */
#define OFF_S (OFF_T + NSTAGE * TGT_STAGE)      /* 81920 */
#define SMEM_DYN (OFF_S + NSTAGE * SRC_STAGE)   /* 82944 */

__device__ __forceinline__ uint32_t smem_u32(const void* p) {
    uint32_t a;
    asm("{ .reg .u64 t; cvta.to.shared.u64 t, %1; cvt.u32.u64 %0, t; }" : "=r"(a) : "l"(p));
    return a;
}

__device__ __forceinline__ void cp16(uint32_t saddr, const void* g) {
    asm volatile("cp.async.cg.shared.global [%0], [%1], 16;" :: "r"(saddr), "l"(g) : "memory");
}
#define CP_COMMIT() asm volatile("cp.async.commit_group;" ::: "memory")
#define CP_WAIT(n)  asm volatile("cp.async.wait_group %0;" :: "n"(n) : "memory")

__device__ __forceinline__ void ldsm_x4(uint32_t (&r)[4], uint32_t addr) {
    asm volatile("ldmatrix.sync.aligned.m8n8.x4.shared.b16 {%0,%1,%2,%3}, [%4];"
                 : "=r"(r[0]), "=r"(r[1]), "=r"(r[2]), "=r"(r[3]) : "r"(addr));
}

__device__ __forceinline__ void mma16816(float (&d)[4], const uint32_t (&a)[4],
                                         uint32_t b0, uint32_t b1) {
    asm volatile(
        "mma.sync.aligned.m16n8k16.row.col.f32.f16.f16.f32 "
        "{%0,%1,%2,%3}, {%4,%5,%6,%7}, {%8,%9}, {%0,%1,%2,%3};"
        : "+f"(d[0]), "+f"(d[1]), "+f"(d[2]), "+f"(d[3])
        : "r"(a[0]), "r"(a[1]), "r"(a[2]), "r"(a[3]), "r"(b0), "r"(b1));
}

__device__ __forceinline__ void sts128(uint32_t addr, uint32_t x, uint32_t y,
                                       uint32_t z, uint32_t w) {
    asm volatile("st.shared.v4.b32 [%0], {%1,%2,%3,%4};"
                 :: "r"(addr), "r"(x), "r"(y), "r"(z), "r"(w) : "memory");
}

__device__ __forceinline__ void lds128(uint32_t (&r)[4], uint32_t addr) {
    asm volatile("ld.shared.v4.b32 {%0,%1,%2,%3}, [%4];"
                 : "=r"(r[0]), "=r"(r[1]), "=r"(r[2]), "=r"(r[3]) : "r"(addr));
}

__device__ __forceinline__ uint32_t h2u(__half2 h) { return *reinterpret_cast<uint32_t*>(&h); }
__device__ __forceinline__ __half2 u2h(uint32_t u) { return *reinterpret_cast<__half2*>(&u); }

// Static fp16 scratch: W [V][D] (2MB), src [B*T][D] (2MB), tgt [B*U][D] (0.5MB)
__device__ __align__(16) __half g_Wh[(size_t)V_ * D_];
__device__ __align__(16) __half g_Sh[(size_t)B_ * T_ * D_];
__device__ __align__(16) __half g_Th[(size_t)B_ * U_ * D_];

#define NW (V_ * D_ / 4)
#define NS (B_ * T_ * D_ / 4)
#define NT (B_ * U_ * D_ / 4)

// convert W/src/tgt to fp16; write lengths tail
__global__ void __launch_bounds__(256) prep_kernel(
    const float* __restrict__ W, const float* __restrict__ src,
    const float* __restrict__ tgt,
    const int* __restrict__ sl, const int* __restrict__ tl,
    float* __restrict__ tail_out, int ntail) {
    int i = blockIdx.x * blockDim.x + threadIdx.x;
    const float4* in;
    uint2* out;
    int j;
    if (i < NW)            { in = (const float4*)W;   out = (uint2*)g_Wh; j = i; }
    else if (i < NW + NS)  { in = (const float4*)src; out = (uint2*)g_Sh; j = i - NW; }
    else                   { in = (const float4*)tgt; out = (uint2*)g_Th; j = i - NW - NS; }
    float4 v = in[j];
    uint2 o;
    o.x = h2u(__floats2half2_rn(v.x, v.y));
    o.y = h2u(__floats2half2_rn(v.z, v.w));
    out[j] = o;
    if (blockIdx.x == 0 && threadIdx.x < (unsigned)ntail) {
        int k = threadIdx.x;
        int val = (k < B_) ? sl[k] : ((k < 2 * B_) ? tl[k - B_] : 0);
        tail_out[k] = (float)val;
    }
}

__global__ void __launch_bounds__(NTHREADS, 2) joiner_gemm(
    const float* __restrict__ bias, float* __restrict__ out) {
    extern __shared__ __align__(128) char smem[];
    const uint32_t S0 = smem_u32(smem);

    const int tid = threadIdx.x;
    const int wid = tid >> 5, lane = tid & 31;
    const int nt = blockIdx.x;   // 0..7  (nt-fast: 8 CTAs share src/tgt slices in L2)
    const int mt = blockIdx.y;   // 0..511
    const int b = mt >> 7;
    const int t0 = (mt & 127) * 2;

    // ---- fill/build roles: thread -> (row r = tid>>2, seg = tid&3, 16B each) ----
    const int r = tid >> 2;         // 0..127
    const int seg = tid & 3;        // 0..3
    const __half* wrow = g_Wh + ((size_t)(nt * TILE_N + r)) * D_ + seg * 8;
    const uint32_t fill_off = (uint32_t)r * PITCH + seg * 16;
    const __half* tgtb = g_Th + ((size_t)(b * U_)) * D_;
    const __half* srcb = g_Sh + ((size_t)(b * T_ + t0)) * D_;
    // buildA per-thread smem offsets (within a staging slot)
    const uint32_t bs_off = (uint32_t)(r >> 6) * PITCH + seg * 16;   // src row 0..1
    const uint32_t bt_off = (uint32_t)(r & 63) * PITCH + seg * 16;   // tgt row 0..63

    // ---- mma-role: 16 warps = 4m x 4n, warp tile 32x32 ----
    const int m0w = (wid & 3) * 32;
    const int n0w = (wid >> 2) * 32;
    const uint32_t a_ld_off = (uint32_t)(m0w + (lane & 15)) * PITCH + (lane >> 4) * 16;
    const uint32_t b_ld_off =
        (uint32_t)(n0w + (lane & 7) + ((lane & 16) >> 1)) * PITCH + ((lane >> 3) & 1) * 16;

    float acc[2][4][4];
#pragma unroll
    for (int mi = 0; mi < 2; mi++)
#pragma unroll
        for (int ni = 0; ni < 4; ni++)
#pragma unroll
            for (int q = 0; q < 4; q++) acc[mi][ni][q] = 0.f;

    // cp.async for one k-stage: B tile (8KB) + tgt slice (4KB) + src slice (128B)
    auto loadStage = [&](int s, int kt) {
        const int k0 = kt * TILE_K;
        cp16(S0 + OFF_B + s * STAGE_BYTES + fill_off, wrow + k0);
        if (tid < 256) {
            // tgt rows 0..63, 4 segs
            cp16(S0 + OFF_T + s * TGT_STAGE + fill_off,
                 tgtb + (size_t)(tid >> 2) * D_ + k0 + seg * 8);
        } else if (tid < 264) {
            int j = tid - 256;  // 0..7: src rows 0..1, 4 segs
            cp16(S0 + OFF_S + s * SRC_STAGE + (uint32_t)(j >> 2) * PITCH + (j & 3) * 16,
                 srcb + (size_t)(j >> 2) * D_ + k0 + (j & 3) * 8);
        }
    };

    // build fp16 A tile for stage kt: 1 x 16B segment per thread
    auto buildA = [&](int kt) {
        const int s = kt & (NSTAGE - 1);
        uint32_t sv[4], tv[4];
        lds128(sv, S0 + OFF_S + s * SRC_STAGE + bs_off);
        lds128(tv, S0 + OFF_T + s * TGT_STAGE + bt_off);
        const __half2 z = __float2half2_rn(0.f);
#pragma unroll
        for (int q = 0; q < 4; q++)
            sv[q] = h2u(__hmax2(__hadd2(u2h(sv[q]), u2h(tv[q])), z));
        sts128(S0 + OFF_A + (kt & 1) * STAGE_BYTES + fill_off, sv[0], sv[1], sv[2], sv[3]);
    };

    // ---- prologue ----
#pragma unroll
    for (int s = 0; s < NSTAGE - 1; s++) {
        loadStage(s, s);
        CP_COMMIT();
    }
    CP_WAIT(2);          // stage 0 complete
    __syncthreads();
    buildA(0);

#pragma unroll 1
    for (int kt = 0; kt < KITERS; kt++) {
        CP_WAIT(1);      // stage kt+1 complete (only newest group pending)
        __syncthreads(); // A(kt) STS visible; staging slot (kt+3)&3 reusable
        if (kt + NSTAGE - 1 < KITERS)
            loadStage((kt + NSTAGE - 1) & (NSTAGE - 1), kt + NSTAGE - 1);
        CP_COMMIT();     // uniform group count
        if (kt + 1 < KITERS) buildA(kt + 1);

        const uint32_t Ab = S0 + OFF_A + (kt & 1) * STAGE_BYTES;
        const uint32_t Bt = S0 + OFF_B + (kt & (NSTAGE - 1)) * STAGE_BYTES;
#pragma unroll
        for (int k16 = 0; k16 < 2; k16++) {
            const uint32_t kb = k16 * 32;
            uint32_t bfr[2][4];
            ldsm_x4(bfr[0], Bt + b_ld_off + kb);
            ldsm_x4(bfr[1], Bt + 16u * PITCH + b_ld_off + kb);
            uint32_t afr[2][4];
            ldsm_x4(afr[0], Ab + a_ld_off + kb);
            ldsm_x4(afr[1], Ab + 16u * PITCH + a_ld_off + kb);
#pragma unroll
            for (int mi = 0; mi < 2; mi++)
#pragma unroll
                for (int ni = 0; ni < 4; ni++)
                    mma16816(acc[mi][ni], afr[mi], bfr[ni >> 1][(ni & 1) * 2],
                             bfr[ni >> 1][(ni & 1) * 2 + 1]);
        }
    }

    // ---- epilogue: add bias, write fp32 ----
    const int g = lane >> 2;
    const int tig = lane & 3;
    const int gn0 = nt * TILE_N + n0w;
    float2 bb[4];
#pragma unroll
    for (int ni = 0; ni < 4; ni++)
        bb[ni] = *reinterpret_cast<const float2*>(bias + gn0 + ni * 8 + tig * 2);

    const size_t rowbase = (size_t)mt * TILE_M + m0w;
#pragma unroll
    for (int mi = 0; mi < 2; mi++) {
        size_t r0 = rowbase + mi * 16 + g;
        size_t r1 = r0 + 8;
#pragma unroll
        for (int ni = 0; ni < 4; ni++) {
            float* p0 = out + r0 * (size_t)V_ + gn0 + ni * 8 + tig * 2;
            float* p1 = out + r1 * (size_t)V_ + gn0 + ni * 8 + tig * 2;
            *reinterpret_cast<float2*>(p0) =
                make_float2(acc[mi][ni][0] + bb[ni].x, acc[mi][ni][1] + bb[ni].y);
            *reinterpret_cast<float2*>(p1) =
                make_float2(acc[mi][ni][2] + bb[ni].x, acc[mi][ni][3] + bb[ni].y);
        }
    }
}

extern "C" void kernel_launch(void* const* d_in, const int* in_sizes, int n_in,
                              void* d_out, int out_size) {
    const float* src  = (const float*)d_in[0];
    const int*   slen = (const int*)d_in[1];
    const float* tgt  = (const float*)d_in[2];
    const int*   tlen = (const int*)d_in[3];
    const float* W    = (const float*)d_in[4];
    const float* bias = (const float*)d_in[5];
    float* out = (float*)d_out;

    long long main_elems = (long long)M_ * V_;
    int ntail = 0;
    if ((long long)out_size > main_elems) {
        ntail = (int)((long long)out_size - main_elems);
        if (ntail > 32) ntail = 32;
    }
    prep_kernel<<<(NW + NS + NT) / 256, 256>>>(W, src, tgt, slen, tlen,
                                               out + main_elems, ntail);

    cudaFuncSetAttribute(joiner_gemm, cudaFuncAttributeMaxDynamicSharedMemorySize, SMEM_DYN);
    dim3 grid(V_ / TILE_N, M_ / TILE_M);  // (8, 512) nt-fast
    joiner_gemm<<<grid, NTHREADS, SMEM_DYN>>>(bias, out);
}

// round 9
// speedup vs baseline: 1.1470x; 1.1470x over previous
#include <cuda_runtime.h>
#include <cuda_fp16.h>
#include <cstdint>

// ---------------------------------------------------------------------------
// RNNT joiner, two-pass:
//   pass 1: Ah[m][d] = fp16(relu(src[b,t,d] + tgt[b,u,d]))
//   pass 2: out = Ah @ Wh^T + bias  (M=65536, N=1024, K=1024, HMMA fp16)
// R8 showed L1TEX crossbar is the binding resource; LDSM traffic is already
// minimal for the 64-reg budget. R9 attacks the per-iteration overhead:
// TILE_K=64 halves barrier/wait count (16 iters instead of 32), NSTAGE=3,
// smem 110.6KB/CTA keeps 2 CTAs/SM (32 warps). GEMM core otherwise = R7:
// 512 thr, 16 warps (4m x 4n of 32x32), nt-fast grid.
// ---------------------------------------------------------------------------

#define B_ 4
#define T_ 256
#define U_ 64
#define D_ 1024
#define V_ 1024
#define M_ (B_ * T_ * U_)

#define TILE_M 128
#define TILE_N 128
#define TILE_K 64
#define KITERS (D_ / TILE_K) /* 16 */
#define NTHREADS 512
#define NSTAGE 3

#define PITCH 144                     /* 128B row + 16B pad: conflict-free ldmatrix */
#define STAGE_BYTES (128 * PITCH)     /* 18432 */
#define SMEM_DYN (2 * NSTAGE * STAGE_BYTES) /* 110592 -> 2 CTAs/SM (221KB + reserve) */

__device__ __forceinline__ uint32_t smem_u32(const void* p) {
    uint32_t a;
    asm("{ .reg .u64 t; cvta.to.shared.u64 t, %1; cvt.u32.u64 %0, t; }" : "=r"(a) : "l"(p));
    return a;
}

__device__ __forceinline__ void cp16(uint32_t saddr, const void* g) {
    asm volatile("cp.async.cg.shared.global [%0], [%1], 16;" :: "r"(saddr), "l"(g) : "memory");
}
#define CP_COMMIT() asm volatile("cp.async.commit_group;" ::: "memory")
#define CP_WAIT(n)  asm volatile("cp.async.wait_group %0;" :: "n"(n) : "memory")

__device__ __forceinline__ void ldsm_x4(uint32_t (&r)[4], uint32_t addr) {
    asm volatile("ldmatrix.sync.aligned.m8n8.x4.shared.b16 {%0,%1,%2,%3}, [%4];"
                 : "=r"(r[0]), "=r"(r[1]), "=r"(r[2]), "=r"(r[3]) : "r"(addr));
}

__device__ __forceinline__ void mma16816(float (&d)[4], const uint32_t (&a)[4],
                                         uint32_t b0, uint32_t b1) {
    asm volatile(
        "mma.sync.aligned.m16n8k16.row.col.f32.f16.f16.f32 "
        "{%0,%1,%2,%3}, {%4,%5,%6,%7}, {%8,%9}, {%0,%1,%2,%3};"
        : "+f"(d[0]), "+f"(d[1]), "+f"(d[2]), "+f"(d[3])
        : "r"(a[0]), "r"(a[1]), "r"(a[2]), "r"(a[3]), "r"(b0), "r"(b1));
}

__device__ __forceinline__ uint32_t h2u(__half2 h) { return *reinterpret_cast<uint32_t*>(&h); }

// Static scratch: W in fp16 (2 MB) and the materialized A operand (128 MB fp16).
__device__ __align__(16) __half g_Wh[(size_t)V_ * D_];
__device__ __align__(16) __half g_Ah[(size_t)M_ * D_];

// convert W + write the appended lengths tail
__global__ void __launch_bounds__(256) prep_kernel(
    const float* __restrict__ W,
    const int* __restrict__ sl, const int* __restrict__ tl,
    float* __restrict__ tail_out, int ntail) {
    int i = blockIdx.x * blockDim.x + threadIdx.x;  // over V*D/4
    float4 v = reinterpret_cast<const float4*>(W)[i];
    __half2* dst = reinterpret_cast<__half2*>(g_Wh);
    dst[2 * i + 0] = __floats2half2_rn(v.x, v.y);
    dst[2 * i + 1] = __floats2half2_rn(v.z, v.w);
    if (blockIdx.x == 0 && threadIdx.x < (unsigned)ntail) {
        int k = threadIdx.x;
        int val = (k < B_) ? sl[k] : ((k < 2 * B_) ? tl[k - B_] : 0);
        tail_out[k] = (float)val;
    }
}

// pass 1: Ah = fp16(relu(src+tgt)); 8 elements per thread
__global__ void __launch_bounds__(256) build_A(const float* __restrict__ src,
                                               const float* __restrict__ tgt) {
    size_t i = (size_t)blockIdx.x * blockDim.x + threadIdx.x;  // over M*D/8
    int dc = (int)(i & (D_ / 8 - 1)) * 8;
    size_t row = i >> 7;
    int u = (int)(row & (U_ - 1));
    int t = (int)((row >> 6) & (T_ - 1));
    int b = (int)(row >> 14);
    const float4* sp = reinterpret_cast<const float4*>(src + ((size_t)(b * T_ + t)) * D_ + dc);
    const float4* tp = reinterpret_cast<const float4*>(tgt + ((size_t)(b * U_ + u)) * D_ + dc);
    float4 s0 = sp[0], s1 = sp[1];
    float4 g0 = tp[0], g1 = tp[1];
    __half2 h0 = __floats2half2_rn(fmaxf(s0.x + g0.x, 0.f), fmaxf(s0.y + g0.y, 0.f));
    __half2 h1 = __floats2half2_rn(fmaxf(s0.z + g0.z, 0.f), fmaxf(s0.w + g0.w, 0.f));
    __half2 h2 = __floats2half2_rn(fmaxf(s1.x + g1.x, 0.f), fmaxf(s1.y + g1.y, 0.f));
    __half2 h3 = __floats2half2_rn(fmaxf(s1.z + g1.z, 0.f), fmaxf(s1.w + g1.w, 0.f));
    *reinterpret_cast<uint4*>(g_Ah + row * D_ + dc) =
        make_uint4(h2u(h0), h2u(h1), h2u(h2), h2u(h3));
}

__global__ void __launch_bounds__(NTHREADS, 2) joiner_gemm(
    const float* __restrict__ bias, float* __restrict__ out) {
    extern __shared__ __align__(128) char smem[];
    const uint32_t A0 = smem_u32(smem);
    const uint32_t Bb0 = A0 + NSTAGE * STAGE_BYTES;

    const int tid = threadIdx.x;
    const int wid = tid >> 5, lane = tid & 31;
    const int nt = blockIdx.x;   // 0..7   (nt-fast: 8 CTAs share one A tile in L2)
    const int mt = blockIdx.y;   // 0..511

    // ---- load-role: thread -> (row = tid>>2, segs tid&3 and (tid&3)+4) ----
    const int lrow = tid >> 2;
    const int lseg = tid & 3;
    const __half* arow = g_Ah + ((size_t)(mt * TILE_M + lrow)) * D_ + lseg * 8;
    const __half* wrow = g_Wh + ((size_t)(nt * TILE_N + lrow)) * D_ + lseg * 8;
    const uint32_t fill_off = (uint32_t)lrow * PITCH + lseg * 16;

    // ---- mma-role: 16 warps = 4m x 4n, warp tile 32x32 ----
    const int m0w = (wid & 3) * 32;
    const int n0w = (wid >> 2) * 32;
    const uint32_t a_ld_off = (uint32_t)(m0w + (lane & 15)) * PITCH + (lane >> 4) * 16;
    const uint32_t b_ld_off =
        (uint32_t)(n0w + (lane & 7) + ((lane & 16) >> 1)) * PITCH + ((lane >> 3) & 1) * 16;

    float acc[2][4][4];
#pragma unroll
    for (int mi = 0; mi < 2; mi++)
#pragma unroll
        for (int ni = 0; ni < 4; ni++)
#pragma unroll
            for (int q = 0; q < 4; q++) acc[mi][ni][q] = 0.f;

    // one k-stage: 128 rows x 128B per operand; 2 cp16 per thread per operand
    auto loadStage = [&](int s, int kt) {
        const int k0 = kt * TILE_K;
        uint32_t da = A0 + s * STAGE_BYTES + fill_off;
        uint32_t db = Bb0 + s * STAGE_BYTES + fill_off;
        cp16(da,      arow + k0);
        cp16(da + 64, arow + k0 + 32);
        cp16(db,      wrow + k0);
        cp16(db + 64, wrow + k0 + 32);
    };

    // prologue: stages 0,1 in flight
    loadStage(0, 0);
    CP_COMMIT();
    loadStage(1, 1);
    CP_COMMIT();

    int cur = 0;  // stage index = kt % 3
#pragma unroll 1
    for (int kt = 0; kt < KITERS; kt++) {
        CP_WAIT(1);          // stage `cur` complete (only newest group pending)
        __syncthreads();
        if (kt + 2 < KITERS) {
            int nxt = cur + 2;
            if (nxt >= NSTAGE) nxt -= NSTAGE;
            loadStage(nxt, kt + 2);
        }
        CP_COMMIT();         // uniform group count

        const uint32_t Ab = A0 + cur * STAGE_BYTES;
        const uint32_t Bt = Bb0 + cur * STAGE_BYTES;
#pragma unroll
        for (int k16 = 0; k16 < 4; k16++) {
            const uint32_t kb = k16 * 32;
            uint32_t bfr[2][4];
            ldsm_x4(bfr[0], Bt + b_ld_off + kb);
            ldsm_x4(bfr[1], Bt + 16u * PITCH + b_ld_off + kb);
            uint32_t afr[2][4];
            ldsm_x4(afr[0], Ab + a_ld_off + kb);
            ldsm_x4(afr[1], Ab + 16u * PITCH + a_ld_off + kb);
#pragma unroll
            for (int mi = 0; mi < 2; mi++)
#pragma unroll
                for (int ni = 0; ni < 4; ni++)
                    mma16816(acc[mi][ni], afr[mi], bfr[ni >> 1][(ni & 1) * 2],
                             bfr[ni >> 1][(ni & 1) * 2 + 1]);
        }
        cur = (cur + 1 == NSTAGE) ? 0 : cur + 1;
    }

    // ---- epilogue: add bias, write fp32 ----
    const int g = lane >> 2;
    const int tig = lane & 3;
    const int gn0 = nt * TILE_N + n0w;
    float2 bb[4];
#pragma unroll
    for (int ni = 0; ni < 4; ni++)
        bb[ni] = *reinterpret_cast<const float2*>(bias + gn0 + ni * 8 + tig * 2);

    const size_t rowbase = (size_t)mt * TILE_M + m0w;
#pragma unroll
    for (int mi = 0; mi < 2; mi++) {
        size_t r0 = rowbase + mi * 16 + g;
        size_t r1 = r0 + 8;
#pragma unroll
        for (int ni = 0; ni < 4; ni++) {
            float* p0 = out + r0 * (size_t)V_ + gn0 + ni * 8 + tig * 2;
            float* p1 = out + r1 * (size_t)V_ + gn0 + ni * 8 + tig * 2;
            *reinterpret_cast<float2*>(p0) =
                make_float2(acc[mi][ni][0] + bb[ni].x, acc[mi][ni][1] + bb[ni].y);
            *reinterpret_cast<float2*>(p1) =
                make_float2(acc[mi][ni][2] + bb[ni].x, acc[mi][ni][3] + bb[ni].y);
        }
    }
}

extern "C" void kernel_launch(void* const* d_in, const int* in_sizes, int n_in,
                              void* d_out, int out_size) {
    const float* src  = (const float*)d_in[0];
    const int*   slen = (const int*)d_in[1];
    const float* tgt  = (const float*)d_in[2];
    const int*   tlen = (const int*)d_in[3];
    const float* W    = (const float*)d_in[4];
    const float* bias = (const float*)d_in[5];
    float* out = (float*)d_out;

    long long main_elems = (long long)M_ * V_;
    int ntail = 0;
    if ((long long)out_size > main_elems) {
        ntail = (int)((long long)out_size - main_elems);
        if (ntail > 32) ntail = 32;
    }
    prep_kernel<<<(V_ * D_ / 4) / 256, 256>>>(W, slen, tlen, out + main_elems, ntail);
    build_A<<<((size_t)M_ * D_ / 8) / 256, 256>>>(src, tgt);

    cudaFuncSetAttribute(joiner_gemm, cudaFuncAttributeMaxDynamicSharedMemorySize, SMEM_DYN);
    dim3 grid(V_ / TILE_N, M_ / TILE_M);  // (8, 512) nt-fast
    joiner_gemm<<<grid, NTHREADS, SMEM_DYN>>>(bias, out);
}

// round 10
// speedup vs baseline: 1.1810x; 1.0296x over previous
#include <cuda_runtime.h>
#include <cuda_fp16.h>
#include <cstdint>

// ---------------------------------------------------------------------------
// RNNT joiner, two-pass:
//   pass 1 (aux): Wh = fp16(W); Ah[m][d] = fp16(relu(src+tgt)); lengths tail
//   pass 2: out = Ah @ Wh^T + bias  (M=65536, N=1024, K=1024, HMMA fp16)
// GEMM: 512 thr, 16 warps (4m x 4n of 32x32), CTA 128x128x64, double-buffered
// cp.async (NSTAGE=2, 73.7KB smem -> 2 CTAs/SM = 32 warps), nt-fast grid.
// 16 k-iterations (half of R7) cuts barrier/wait overhead; PITCH=144 keeps
// ldmatrix conflict-free for 128B rows.
// ---------------------------------------------------------------------------

#define B_ 4
#define T_ 256
#define U_ 64
#define D_ 1024
#define V_ 1024
#define M_ (B_ * T_ * U_)

#define TILE_M 128
#define TILE_N 128
#define TILE_K 64
#define KITERS (D_ / TILE_K) /* 16 */
#define NTHREADS 512
#define NSTAGE 2

#define PITCH 144                     /* 128B row + 16B pad: conflict-free ldmatrix */
#define STAGE_BYTES (128 * PITCH)     /* 18432 */
#define SMEM_DYN (2 * NSTAGE * STAGE_BYTES) /* 73728 -> 2 CTAs/SM easily */

__device__ __forceinline__ uint32_t smem_u32(const void* p) {
    uint32_t a;
    asm("{ .reg .u64 t; cvta.to.shared.u64 t, %1; cvt.u32.u64 %0, t; }" : "=r"(a) : "l"(p));
    return a;
}

__device__ __forceinline__ void cp16(uint32_t saddr, const void* g) {
    asm volatile("cp.async.cg.shared.global [%0], [%1], 16;" :: "r"(saddr), "l"(g) : "memory");
}
#define CP_COMMIT() asm volatile("cp.async.commit_group;" ::: "memory")
#define CP_WAIT(n)  asm volatile("cp.async.wait_group %0;" :: "n"(n) : "memory")

__device__ __forceinline__ void ldsm_x4(uint32_t (&r)[4], uint32_t addr) {
    asm volatile("ldmatrix.sync.aligned.m8n8.x4.shared.b16 {%0,%1,%2,%3}, [%4];"
                 : "=r"(r[0]), "=r"(r[1]), "=r"(r[2]), "=r"(r[3]) : "r"(addr));
}

__device__ __forceinline__ void mma16816(float (&d)[4], const uint32_t (&a)[4],
                                         uint32_t b0, uint32_t b1) {
    asm volatile(
        "mma.sync.aligned.m16n8k16.row.col.f32.f16.f16.f32 "
        "{%0,%1,%2,%3}, {%4,%5,%6,%7}, {%8,%9}, {%0,%1,%2,%3};"
        : "+f"(d[0]), "+f"(d[1]), "+f"(d[2]), "+f"(d[3])
        : "r"(a[0]), "r"(a[1]), "r"(a[2]), "r"(a[3]), "r"(b0), "r"(b1));
}

__device__ __forceinline__ uint32_t h2u(__half2 h) { return *reinterpret_cast<uint32_t*>(&h); }

// Static scratch: W in fp16 (2 MB) and the materialized A operand (128 MB fp16).
__device__ __align__(16) __half g_Wh[(size_t)V_ * D_];
__device__ __align__(16) __half g_Ah[(size_t)M_ * D_];

#define NW_BLOCKS (V_ * D_ / 4 / 256)            /* 1024 conversion blocks */
#define NA_BLOCKS ((int)((size_t)M_ * D_ / 8 / 256)) /* 32768 build blocks */

// merged aux: W->fp16 conversion, A materialization, lengths tail
__global__ void __launch_bounds__(256) aux_kernel(
    const float* __restrict__ W, const float* __restrict__ src,
    const float* __restrict__ tgt,
    const int* __restrict__ sl, const int* __restrict__ tl,
    float* __restrict__ tail_out, int ntail) {
    int blk = blockIdx.x;
    if (blk < NW_BLOCKS) {
        int i = blk * 256 + threadIdx.x;  // over V*D/4
        float4 v = reinterpret_cast<const float4*>(W)[i];
        __half2* dst = reinterpret_cast<__half2*>(g_Wh);
        dst[2 * i + 0] = __floats2half2_rn(v.x, v.y);
        dst[2 * i + 1] = __floats2half2_rn(v.z, v.w);
        if (blk == 0 && threadIdx.x < (unsigned)ntail) {
            int k = threadIdx.x;
            int val = (k < B_) ? sl[k] : ((k < 2 * B_) ? tl[k - B_] : 0);
            tail_out[k] = (float)val;
        }
        return;
    }
    size_t i = (size_t)(blk - NW_BLOCKS) * 256 + threadIdx.x;  // over M*D/8
    int dc = (int)(i & (D_ / 8 - 1)) * 8;
    size_t row = i >> 7;
    int u = (int)(row & (U_ - 1));
    int t = (int)((row >> 6) & (T_ - 1));
    int b = (int)(row >> 14);
    const float4* sp = reinterpret_cast<const float4*>(src + ((size_t)(b * T_ + t)) * D_ + dc);
    const float4* tp = reinterpret_cast<const float4*>(tgt + ((size_t)(b * U_ + u)) * D_ + dc);
    float4 s0 = sp[0], s1 = sp[1];
    float4 g0 = tp[0], g1 = tp[1];
    __half2 h0 = __floats2half2_rn(fmaxf(s0.x + g0.x, 0.f), fmaxf(s0.y + g0.y, 0.f));
    __half2 h1 = __floats2half2_rn(fmaxf(s0.z + g0.z, 0.f), fmaxf(s0.w + g0.w, 0.f));
    __half2 h2 = __floats2half2_rn(fmaxf(s1.x + g1.x, 0.f), fmaxf(s1.y + g1.y, 0.f));
    __half2 h3 = __floats2half2_rn(fmaxf(s1.z + g1.z, 0.f), fmaxf(s1.w + g1.w, 0.f));
    *reinterpret_cast<uint4*>(g_Ah + row * D_ + dc) =
        make_uint4(h2u(h0), h2u(h1), h2u(h2), h2u(h3));
}

__global__ void __launch_bounds__(NTHREADS, 2) joiner_gemm(
    const float* __restrict__ bias, float* __restrict__ out) {
    extern __shared__ __align__(128) char smem[];
    const uint32_t A0 = smem_u32(smem);
    const uint32_t Bb0 = A0 + NSTAGE * STAGE_BYTES;

    const int tid = threadIdx.x;
    const int wid = tid >> 5, lane = tid & 31;
    const int nt = blockIdx.x;   // 0..7   (nt-fast: 8 CTAs share one A tile in L2)
    const int mt = blockIdx.y;   // 0..511

    // ---- load-role: thread -> (row = tid>>2, segs at seg*16 and seg*16+64) ----
    const int lrow = tid >> 2;
    const int lseg = tid & 3;
    const __half* arow = g_Ah + ((size_t)(mt * TILE_M + lrow)) * D_ + lseg * 8;
    const __half* wrow = g_Wh + ((size_t)(nt * TILE_N + lrow)) * D_ + lseg * 8;
    const uint32_t fill_off = (uint32_t)lrow * PITCH + lseg * 16;

    // ---- mma-role: 16 warps = 4m x 4n, warp tile 32x32 ----
    const int m0w = (wid & 3) * 32;
    const int n0w = (wid >> 2) * 32;
    const uint32_t a_ld_off = (uint32_t)(m0w + (lane & 15)) * PITCH + (lane >> 4) * 16;
    const uint32_t b_ld_off =
        (uint32_t)(n0w + (lane & 7) + ((lane & 16) >> 1)) * PITCH + ((lane >> 3) & 1) * 16;

    float acc[2][4][4];
#pragma unroll
    for (int mi = 0; mi < 2; mi++)
#pragma unroll
        for (int ni = 0; ni < 4; ni++)
#pragma unroll
            for (int q = 0; q < 4; q++) acc[mi][ni][q] = 0.f;

    // one k-stage: 128 rows x 128B per operand; 2 cp16 per thread per operand
    auto loadStage = [&](int s, int kt) {
        const int k0 = kt * TILE_K;
        uint32_t da = A0 + s * STAGE_BYTES + fill_off;
        uint32_t db = Bb0 + s * STAGE_BYTES + fill_off;
        cp16(da,      arow + k0);
        cp16(da + 64, arow + k0 + 32);
        cp16(db,      wrow + k0);
        cp16(db + 64, wrow + k0 + 32);
    };

    // prologue: stage 0 in flight
    loadStage(0, 0);
    CP_COMMIT();

#pragma unroll 1
    for (int kt = 0; kt < KITERS; kt++) {
        const int cur = kt & 1;
        CP_WAIT(0);          // stage kt resident
        __syncthreads();     // visible to all warps; prior stage fully consumed
        if (kt + 1 < KITERS) {
            loadStage(cur ^ 1, kt + 1);   // overlaps with compute below
            CP_COMMIT();
        }

        const uint32_t Ab = A0 + cur * STAGE_BYTES;
        const uint32_t Bt = Bb0 + cur * STAGE_BYTES;
#pragma unroll
        for (int k16 = 0; k16 < 4; k16++) {
            const uint32_t kb = k16 * 32;
            uint32_t bfr[2][4];
            ldsm_x4(bfr[0], Bt + b_ld_off + kb);
            ldsm_x4(bfr[1], Bt + 16u * PITCH + b_ld_off + kb);
            uint32_t afr[2][4];
            ldsm_x4(afr[0], Ab + a_ld_off + kb);
            ldsm_x4(afr[1], Ab + 16u * PITCH + a_ld_off + kb);
#pragma unroll
            for (int mi = 0; mi < 2; mi++)
#pragma unroll
                for (int ni = 0; ni < 4; ni++)
                    mma16816(acc[mi][ni], afr[mi], bfr[ni >> 1][(ni & 1) * 2],
                             bfr[ni >> 1][(ni & 1) * 2 + 1]);
        }
    }

    // ---- epilogue: add bias, write fp32 ----
    const int g = lane >> 2;
    const int tig = lane & 3;
    const int gn0 = nt * TILE_N + n0w;
    float2 bb[4];
#pragma unroll
    for (int ni = 0; ni < 4; ni++)
        bb[ni] = *reinterpret_cast<const float2*>(bias + gn0 + ni * 8 + tig * 2);

    const size_t rowbase = (size_t)mt * TILE_M + m0w;
#pragma unroll
    for (int mi = 0; mi < 2; mi++) {
        size_t r0 = rowbase + mi * 16 + g;
        size_t r1 = r0 + 8;
#pragma unroll
        for (int ni = 0; ni < 4; ni++) {
            float* p0 = out + r0 * (size_t)V_ + gn0 + ni * 8 + tig * 2;
            float* p1 = out + r1 * (size_t)V_ + gn0 + ni * 8 + tig * 2;
            *reinterpret_cast<float2*>(p0) =
                make_float2(acc[mi][ni][0] + bb[ni].x, acc[mi][ni][1] + bb[ni].y);
            *reinterpret_cast<float2*>(p1) =
                make_float2(acc[mi][ni][2] + bb[ni].x, acc[mi][ni][3] + bb[ni].y);
        }
    }
}

extern "C" void kernel_launch(void* const* d_in, const int* in_sizes, int n_in,
                              void* d_out, int out_size) {
    const float* src  = (const float*)d_in[0];
    const int*   slen = (const int*)d_in[1];
    const float* tgt  = (const float*)d_in[2];
    const int*   tlen = (const int*)d_in[3];
    const float* W    = (const float*)d_in[4];
    const float* bias = (const float*)d_in[5];
    float* out = (float*)d_out;

    long long main_elems = (long long)M_ * V_;
    int ntail = 0;
    if ((long long)out_size > main_elems) {
        ntail = (int)((long long)out_size - main_elems);
        if (ntail > 32) ntail = 32;
    }
    aux_kernel<<<NW_BLOCKS + NA_BLOCKS, 256>>>(W, src, tgt, slen, tlen,
                                               out + main_elems, ntail);

    cudaFuncSetAttribute(joiner_gemm, cudaFuncAttributeMaxDynamicSharedMemorySize, SMEM_DYN);
    dim3 grid(V_ / TILE_N, M_ / TILE_M);  // (8, 512) nt-fast
    joiner_gemm<<<grid, NTHREADS, SMEM_DYN>>>(bias, out);
}